// round 1
// baseline (speedup 1.0000x reference)
#include <cuda_runtime.h>
#include <cuda_bf16.h>
#include <math.h>

// Problem constants
#define BATCH 8
#define SEQ   2048
#define HID   1024
#define WSIZE 64
#define NEG_INF (-1e9f)

// ---------------------------------------------------------------------------
// Scratch: Q' = repr @ W   [BATCH*SEQ, HID]  (64 MB)
// ---------------------------------------------------------------------------
__device__ float g_qw[BATCH * SEQ * HID];

// ---------------------------------------------------------------------------
// Kernel 1: SGEMM  C[M,N] = A[M,K] * B[K,N]   (fp32)
// M = 16384, N = 1024, K = 1024
// 128x128 block tile, BK=16, 256 threads, 8x8 per-thread micro-tile
// ---------------------------------------------------------------------------
#define BM 128
#define BN 128
#define BK 16

__global__ __launch_bounds__(256, 1)
void sgemm_kernel(const float* __restrict__ A, const float* __restrict__ B,
                  float* __restrict__ C, int M, int N, int K)
{
    __shared__ float As[BK][BM];
    __shared__ float Bs[BK][BN];

    const int tid = threadIdx.x;
    const int bm  = blockIdx.y;
    const int bn  = blockIdx.x;

    const int tx = tid % 16;       // col group (8 cols each)
    const int ty = tid / 16;       // row group (8 rows each)

    const float* Ab = A + (size_t)bm * BM * K;
    const float* Bb = B + (size_t)bn * BN;

    // Load mapping
    const int ar  = tid / 4;             // 0..63
    const int ac4 = (tid % 4) * 4;       // 0,4,8,12
    const int br  = tid / 32;            // 0..7
    const int bc4 = (tid % 32) * 4;      // 0..124

    float acc[8][8];
#pragma unroll
    for (int i = 0; i < 8; i++)
#pragma unroll
        for (int j = 0; j < 8; j++) acc[i][j] = 0.f;

    for (int k0 = 0; k0 < K; k0 += BK) {
        // A tile -> As (transposed)
#pragma unroll
        for (int t = 0; t < 2; t++) {
            float4 v = *(const float4*)(Ab + (size_t)(ar + 64 * t) * K + k0 + ac4);
            As[ac4 + 0][ar + 64 * t] = v.x;
            As[ac4 + 1][ar + 64 * t] = v.y;
            As[ac4 + 2][ar + 64 * t] = v.z;
            As[ac4 + 3][ar + 64 * t] = v.w;
        }
        // B tile -> Bs
#pragma unroll
        for (int t = 0; t < 2; t++) {
            *(float4*)&Bs[br + 8 * t][bc4] =
                *(const float4*)(Bb + (size_t)(k0 + br + 8 * t) * N + bc4);
        }
        __syncthreads();

#pragma unroll
        for (int k = 0; k < BK; k++) {
            float a[8], b[8];
#pragma unroll
            for (int i = 0; i < 8; i++) a[i] = As[k][ty * 8 + i];
#pragma unroll
            for (int j = 0; j < 8; j++) b[j] = Bs[k][tx * 8 + j];
#pragma unroll
            for (int i = 0; i < 8; i++)
#pragma unroll
                for (int j = 0; j < 8; j++) acc[i][j] += a[i] * b[j];
        }
        __syncthreads();
    }

    float* Cb = C + (size_t)(bm * BM + ty * 8) * N + bn * BN + tx * 8;
#pragma unroll
    for (int i = 0; i < 8; i++) {
#pragma unroll
        for (int j = 0; j < 8; j += 4) {
            float4 v = make_float4(acc[i][j], acc[i][j + 1], acc[i][j + 2], acc[i][j + 3]);
            *(float4*)(Cb + (size_t)i * N + j) = v;
        }
    }
}

// ---------------------------------------------------------------------------
// Kernel 2: banded attention (fused QK^T, masked softmax, PV, relu+residual)
// One block per (64-query tile, batch). Keys span [q0-64, q0+127] = 192 keys.
// Dynamic smem:
//   S  [64][193]  scores/probs                (12352 floats)
//   union {
//     QS [64][33] + KS [192][33]  (QK phase)  (8448 floats)
//     R  [192][64]                (PV phase)  (12288 floats)
//   }
// total = 24640 floats = 98560 bytes
// ---------------------------------------------------------------------------
#define TQ 64
#define TK 192
#define SW 193   // padded S row stride

__global__ __launch_bounds__(256, 1)
void attn_kernel(const float* __restrict__ qw, const float* __restrict__ repr,
                 float* __restrict__ out)
{
    extern __shared__ float sm[];
    float* S  = sm;                    // [64][SW]
    float* QS = sm + TQ * SW;          // [64][33]
    float* KS = QS + TQ * 33;          // [192][33]
    float* R  = sm + TQ * SW;          // [192][64]  (aliases QS/KS)

    const int b   = blockIdx.y;
    const int q0  = blockIdx.x * TQ;
    const int k0  = q0 - WSIZE;        // first key index (may be negative)
    const int tid = threadIdx.x;

    const float* qwB = qw   + (size_t)b * SEQ * HID;
    const float* reB = repr + (size_t)b * SEQ * HID;
    float*       oB  = out  + (size_t)b * SEQ * HID;

    // ---------------- Phase 1: S = Q' K^T (banded tile) -------------------
    const int tr = tid / 16;   // 0..15 -> rows 4*tr..4*tr+3
    const int tc = tid % 16;   // 0..15 -> cols 12*tc..12*tc+11
    float acc[4][12];
#pragma unroll
    for (int i = 0; i < 4; i++)
#pragma unroll
        for (int j = 0; j < 12; j++) acc[i][j] = 0.f;

    for (int dk = 0; dk < HID; dk += 32) {
        // load Q' tile [64 x 32]
        for (int t = tid; t < TQ * 32; t += 256) {
            int r = t >> 5, c = t & 31;
            QS[r * 33 + c] = qwB[(size_t)(q0 + r) * HID + dk + c];
        }
        // load K tile [192 x 32] (zero-fill OOB rows; masked later anyway)
        for (int t = tid; t < TK * 32; t += 256) {
            int r = t >> 5, c = t & 31;
            int j = k0 + r;
            KS[r * 33 + c] = (j >= 0 && j < SEQ)
                             ? reB[(size_t)j * HID + dk + c] : 0.f;
        }
        __syncthreads();

#pragma unroll 8
        for (int kk = 0; kk < 32; kk++) {
            float qv[4], kv[12];
#pragma unroll
            for (int i = 0; i < 4; i++)  qv[i] = QS[(4 * tr + i) * 33 + kk];
#pragma unroll
            for (int j = 0; j < 12; j++) kv[j] = KS[(12 * tc + j) * 33 + kk];
#pragma unroll
            for (int i = 0; i < 4; i++)
#pragma unroll
                for (int j = 0; j < 12; j++) acc[i][j] += qv[i] * kv[j];
        }
        __syncthreads();
    }

#pragma unroll
    for (int i = 0; i < 4; i++)
#pragma unroll
        for (int j = 0; j < 12; j++)
            S[(4 * tr + i) * SW + 12 * tc + j] = acc[i][j];
    __syncthreads();

    // ---------------- Phase 2: masked softmax over 192 keys ----------------
    {
        const int row  = tid >> 2;        // 0..63
        const int quad = tid & 3;         // 4 threads per row, 48 cols each
        const int cbeg = quad * 48;
        const int i_gl = q0 + row;

        float mx = -3.4e38f;
#pragma unroll 8
        for (int c = cbeg; c < cbeg + 48; c++) {
            int j = k0 + c;
            int d = i_gl - j;
            bool valid = (j >= 0) && (j < SEQ) && (d <= WSIZE) && (d >= -WSIZE);
            float v = valid ? S[row * SW + c] : NEG_INF;
            S[row * SW + c] = v;
            mx = fmaxf(mx, v);
        }
        mx = fmaxf(mx, __shfl_xor_sync(0xffffffffu, mx, 1));
        mx = fmaxf(mx, __shfl_xor_sync(0xffffffffu, mx, 2));

        float sum = 0.f;
#pragma unroll 8
        for (int c = cbeg; c < cbeg + 48; c++) {
            float e = __expf(S[row * SW + c] - mx);
            S[row * SW + c] = e;
            sum += e;
        }
        sum += __shfl_xor_sync(0xffffffffu, sum, 1);
        sum += __shfl_xor_sync(0xffffffffu, sum, 2);
        float inv = 1.f / sum;
#pragma unroll 8
        for (int c = cbeg; c < cbeg + 48; c++)
            S[row * SW + c] *= inv;
    }
    __syncthreads();

    // ---------------- Phase 3: out = repr + relu(P @ K_repr) ---------------
    {
        const int rg = tid >> 3;  // 0..31 -> rows 2*rg, 2*rg+1
        const int cg = tid & 7;   // 0..7  -> cols 8*cg..8*cg+7

        for (int d0 = 0; d0 < HID; d0 += 64) {
            // load repr chunk [192 x 64]
            for (int t = tid; t < TK * 64; t += 256) {
                int r = t >> 6, c = t & 63;
                int j = k0 + r;
                R[t] = (j >= 0 && j < SEQ)
                       ? reB[(size_t)j * HID + d0 + c] : 0.f;
            }
            __syncthreads();

            float o0[8], o1[8];
#pragma unroll
            for (int u = 0; u < 8; u++) { o0[u] = 0.f; o1[u] = 0.f; }

#pragma unroll 4
            for (int k = 0; k < TK; k++) {
                float p0 = S[(2 * rg)     * SW + k];
                float p1 = S[(2 * rg + 1) * SW + k];
#pragma unroll
                for (int u = 0; u < 8; u++) {
                    float rv = R[k * 64 + 8 * cg + u];
                    o0[u] += p0 * rv;
                    o1[u] += p1 * rv;
                }
            }

            const int i0 = q0 + 2 * rg;
            const int c0 = d0 + 8 * cg;
#pragma unroll
            for (int u = 0; u < 8; u++) {
                oB[(size_t)i0 * HID + c0 + u] =
                    reB[(size_t)i0 * HID + c0 + u] + fmaxf(o0[u], 0.f);
                oB[(size_t)(i0 + 1) * HID + c0 + u] =
                    reB[(size_t)(i0 + 1) * HID + c0 + u] + fmaxf(o1[u], 0.f);
            }
            __syncthreads();
        }
    }
}

// ---------------------------------------------------------------------------
// Launch
// ---------------------------------------------------------------------------
extern "C" void kernel_launch(void* const* d_in, const int* in_sizes, int n_in,
                              void* d_out, int out_size)
{
    const float* repr = (const float*)d_in[0];   // [8, 2048, 1024]
    const float* W    = (const float*)d_in[1];   // [1024, 1024]
    float* out        = (float*)d_out;           // [8, 2048, 1024]

    float* qw = nullptr;
    cudaGetSymbolAddress((void**)&qw, g_qw);

    // Kernel 1: Q' = repr @ W
    {
        dim3 grid(HID / BN, (BATCH * SEQ) / BM);  // (8, 128)
        sgemm_kernel<<<grid, 256>>>(repr, W, qw, BATCH * SEQ, HID, HID);
    }

    // Kernel 2: fused banded attention
    {
        const int smem_bytes = (TQ * SW + TK * 64) * (int)sizeof(float); // 98560
        static int attr_set = 0;
        (void)attr_set;
        cudaFuncSetAttribute(attn_kernel,
                             cudaFuncAttributeMaxDynamicSharedMemorySize,
                             smem_bytes);
        dim3 grid(SEQ / TQ, BATCH);               // (32, 8)
        attn_kernel<<<grid, 256, smem_bytes>>>(qw, repr, out);
    }
}

// round 4
// speedup vs baseline: 1.3220x; 1.3220x over previous
#include <cuda_runtime.h>
#include <cuda_bf16.h>
#include <math.h>
#include <stdint.h>

// Problem constants
#define BATCH 8
#define SEQ   2048
#define HID   1024
#define WSIZE 64
#define NEG_INF (-1e9f)

// ---------------------------------------------------------------------------
// Device scratch
// ---------------------------------------------------------------------------
__device__ float         g_qw[BATCH * SEQ * HID];            // Q' fp32 (64MB)
__device__ __nv_bfloat16 g_ah[BATCH * SEQ * HID];            // repr hi (32MB)
__device__ __nv_bfloat16 g_al[BATCH * SEQ * HID];            // repr lo (32MB)
__device__ __nv_bfloat16 g_bh[HID * HID];                    // W^T hi  (2MB)
__device__ __nv_bfloat16 g_bl[HID * HID];                    // W^T lo  (2MB)

// ---------------------------------------------------------------------------
// Helpers
// ---------------------------------------------------------------------------
__device__ __forceinline__ uint32_t smem_u32(const void* p) {
    uint32_t a;
    asm("{ .reg .u64 t; cvta.to.shared.u64 t, %1; cvt.u32.u64 %0, t; }"
        : "=r"(a) : "l"(p));
    return a;
}
__device__ __forceinline__ void cp16(uint32_t dst, const void* src) {
    asm volatile("cp.async.cg.shared.global [%0], [%1], 16;\n" :: "r"(dst), "l"(src));
}
#define CP_COMMIT() asm volatile("cp.async.commit_group;\n" ::: "memory")
#define CP_WAIT(n)  asm volatile("cp.async.wait_group %0;\n" :: "n"(n) : "memory")

__device__ __forceinline__ void ldsm_x4(uint32_t addr, uint32_t* r) {
    asm volatile("ldmatrix.sync.aligned.m8n8.x4.shared.b16 {%0,%1,%2,%3}, [%4];"
                 : "=r"(r[0]), "=r"(r[1]), "=r"(r[2]), "=r"(r[3]) : "r"(addr));
}
__device__ __forceinline__ void mma_bf16(float* d, const uint32_t* a, const uint32_t* b) {
    asm volatile("mma.sync.aligned.m16n8k16.row.col.f32.bf16.bf16.f32 "
                 "{%0,%1,%2,%3}, {%4,%5,%6,%7}, {%8,%9}, {%0,%1,%2,%3};"
                 : "+f"(d[0]), "+f"(d[1]), "+f"(d[2]), "+f"(d[3])
                 : "r"(a[0]), "r"(a[1]), "r"(a[2]), "r"(a[3]),
                   "r"(b[0]), "r"(b[1]));
}

// ---------------------------------------------------------------------------
// Split kernels
// ---------------------------------------------------------------------------
__global__ __launch_bounds__(256)
void split_repr_kernel(const float* __restrict__ x,
                       __nv_bfloat16* __restrict__ hi,
                       __nv_bfloat16* __restrict__ lo)
{
    int i = (blockIdx.x * 256 + threadIdx.x) * 4;
    float4 v = *(const float4*)(x + i);
    __nv_bfloat16 h0 = __float2bfloat16_rn(v.x);
    __nv_bfloat16 h1 = __float2bfloat16_rn(v.y);
    __nv_bfloat16 h2 = __float2bfloat16_rn(v.z);
    __nv_bfloat16 h3 = __float2bfloat16_rn(v.w);
    __nv_bfloat16 l0 = __float2bfloat16_rn(v.x - __bfloat162float(h0));
    __nv_bfloat16 l1 = __float2bfloat16_rn(v.y - __bfloat162float(h1));
    __nv_bfloat16 l2 = __float2bfloat16_rn(v.z - __bfloat162float(h2));
    __nv_bfloat16 l3 = __float2bfloat16_rn(v.w - __bfloat162float(h3));
    __nv_bfloat162 hp0 = __nv_bfloat162(h0, h1), hp1 = __nv_bfloat162(h2, h3);
    __nv_bfloat162 lp0 = __nv_bfloat162(l0, l1), lp1 = __nv_bfloat162(l2, l3);
    *(uint2*)(hi + i) = make_uint2(*(uint32_t*)&hp0, *(uint32_t*)&hp1);
    *(uint2*)(lo + i) = make_uint2(*(uint32_t*)&lp0, *(uint32_t*)&lp1);
}

// W^T split: bt[n][k] = split(W[k][n])
__global__ __launch_bounds__(256)
void wsplit_kernel(const float* __restrict__ W,
                   __nv_bfloat16* __restrict__ bh,
                   __nv_bfloat16* __restrict__ bl)
{
    int idx = blockIdx.x * 256 + threadIdx.x;
    int n = idx >> 10, k = idx & 1023;
    float x = W[k * HID + n];
    __nv_bfloat16 h = __float2bfloat16_rn(x);
    __nv_bfloat16 l = __float2bfloat16_rn(x - __bfloat162float(h));
    bh[idx] = h; bl[idx] = l;
}

// ---------------------------------------------------------------------------
// HMMA split-bf16 GEMM:  C[16384,1024] = A @ B^T   (B stored [n][k])
// Block 128x128, BK=32, 8 warps (4x2), warp tile 32x64, double-buffer cp.async
// smem row stride 80B (40 bf16): conflict-free ldmatrix
// ---------------------------------------------------------------------------
#define GBM 128
#define GBN 128
#define GBK 32
#define ROWB 80                   // bytes per smem row (32 bf16 data + pad)
#define GS_AH 0
#define GS_AL (128 * ROWB)        // 10240
#define GS_BH (2 * 128 * ROWB)    // 20480
#define GS_BL (3 * 128 * ROWB)    // 30720
#define GS_SZ (4 * 128 * ROWB)    // 40960 per stage

__global__ __launch_bounds__(256, 1)
void gemm_hmma_kernel(const __nv_bfloat16* __restrict__ Ah,
                      const __nv_bfloat16* __restrict__ Al,
                      const __nv_bfloat16* __restrict__ Bh,
                      const __nv_bfloat16* __restrict__ Bl,
                      float* __restrict__ C)
{
    extern __shared__ char dynsm[];
    const uint32_t sbase = smem_u32(dynsm);
    const int tid   = threadIdx.x;
    const int wid   = tid >> 5;
    const int lane  = tid & 31;
    const int warpM = wid >> 1;          // 0..3  (32 rows each)
    const int warpN = wid & 1;           // 0..1  (64 cols each)

    const int rowA = blockIdx.y * GBM;
    const int colB = blockIdx.x * GBN;

    float acc[2][8][4];
#pragma unroll
    for (int mt = 0; mt < 2; mt++)
#pragma unroll
        for (int nt = 0; nt < 8; nt++)
#pragma unroll
            for (int q = 0; q < 4; q++) acc[mt][nt][q] = 0.f;

    // stage loader: 2048 x 16B chunks / 256 threads = 8 per thread
    auto load_stage = [&](int c, int stage) {
        const int k0 = c * GBK;
        const uint32_t tb = sbase + stage * GS_SZ;
#pragma unroll
        for (int i = 0; i < 2; i++) {
            int e = tid + i * 256;               // 0..511
            int r = e >> 2, cc = e & 3;
            uint32_t d = (uint32_t)(r * ROWB + cc * 16);
            const __nv_bfloat16* pa = Ah + (size_t)(rowA + r) * HID + k0 + cc * 8;
            const __nv_bfloat16* pl = Al + (size_t)(rowA + r) * HID + k0 + cc * 8;
            const __nv_bfloat16* pb = Bh + (size_t)(colB + r) * HID + k0 + cc * 8;
            const __nv_bfloat16* pm = Bl + (size_t)(colB + r) * HID + k0 + cc * 8;
            cp16(tb + GS_AH + d, pa);
            cp16(tb + GS_AL + d, pl);
            cp16(tb + GS_BH + d, pb);
            cp16(tb + GS_BL + d, pm);
        }
        CP_COMMIT();
    };

    load_stage(0, 0);

    const int NK = HID / GBK;   // 32
    for (int c = 0; c < NK; c++) {
        if (c + 1 < NK) {
            load_stage(c + 1, (c + 1) & 1);
            CP_WAIT(1);
        } else {
            CP_WAIT(0);
        }
        __syncthreads();

        const uint32_t tb = sbase + (c & 1) * GS_SZ;
        // A frag addresses (same lane pattern both k-steps; kk adds 32B)
        const uint32_t a_l = (uint32_t)((warpM * 32 + (lane & 15)) * ROWB + (lane >> 4) * 16);
        // B frag address pieces
        const int g  = lane >> 3;             // 0..3
        const uint32_t b_row = (uint32_t)(warpN * 64 + ((g >> 1) << 3) + (lane & 7));
        const uint32_t b_l   = b_row * ROWB + (uint32_t)((g & 1) * 16);

#pragma unroll
        for (int kk = 0; kk < 2; kk++) {
            const uint32_t ko = (uint32_t)(kk * 32);
            uint32_t ah[2][4], al[2][4], bhf[8][2], blf[8][2];
#pragma unroll
            for (int mt = 0; mt < 2; mt++) {
                uint32_t off = a_l + (uint32_t)(mt * 16 * ROWB) + ko;
                ldsm_x4(tb + GS_AH + off, ah[mt]);
                ldsm_x4(tb + GS_AL + off, al[mt]);
            }
#pragma unroll
            for (int np = 0; np < 4; np++) {
                uint32_t off = b_l + (uint32_t)(np * 16 * ROWB) + ko;
                uint32_t r[4];
                ldsm_x4(tb + GS_BH + off, r);
                bhf[2 * np][0] = r[0]; bhf[2 * np][1] = r[1];
                bhf[2 * np + 1][0] = r[2]; bhf[2 * np + 1][1] = r[3];
                ldsm_x4(tb + GS_BL + off, r);
                blf[2 * np][0] = r[0]; blf[2 * np][1] = r[1];
                blf[2 * np + 1][0] = r[2]; blf[2 * np + 1][1] = r[3];
            }
#pragma unroll
            for (int mt = 0; mt < 2; mt++) {
#pragma unroll
                for (int nt = 0; nt < 8; nt++) {
                    mma_bf16(acc[mt][nt], ah[mt], bhf[nt]);
                    mma_bf16(acc[mt][nt], ah[mt], blf[nt]);
                    mma_bf16(acc[mt][nt], al[mt], bhf[nt]);
                }
            }
        }
        __syncthreads();
    }

    // Epilogue: direct float2 stores
    const int r0 = rowA + warpM * 32 + (lane >> 2);
    const int c0 = colB + warpN * 64 + (lane & 3) * 2;
#pragma unroll
    for (int mt = 0; mt < 2; mt++) {
#pragma unroll
        for (int nt = 0; nt < 8; nt++) {
            int rr = r0 + mt * 16;
            int cc = c0 + nt * 8;
            *(float2*)(C + (size_t)rr * HID + cc) =
                make_float2(acc[mt][nt][0], acc[mt][nt][1]);
            *(float2*)(C + (size_t)(rr + 8) * HID + cc) =
                make_float2(acc[mt][nt][2], acc[mt][nt][3]);
        }
    }
}

// ---------------------------------------------------------------------------
// Kernel 2: banded attention (unchanged from passing R1)
// ---------------------------------------------------------------------------
#define TQ 64
#define TK 192
#define SW 193

__global__ __launch_bounds__(256, 1)
void attn_kernel(const float* __restrict__ qw, const float* __restrict__ repr,
                 float* __restrict__ out)
{
    extern __shared__ float sm[];
    float* S  = sm;
    float* QS = sm + TQ * SW;
    float* KS = QS + TQ * 33;
    float* R  = sm + TQ * SW;

    const int b   = blockIdx.y;
    const int q0  = blockIdx.x * TQ;
    const int k0  = q0 - WSIZE;
    const int tid = threadIdx.x;

    const float* qwB = qw   + (size_t)b * SEQ * HID;
    const float* reB = repr + (size_t)b * SEQ * HID;
    float*       oB  = out  + (size_t)b * SEQ * HID;

    const int tr = tid / 16;
    const int tc = tid % 16;
    float acc[4][12];
#pragma unroll
    for (int i = 0; i < 4; i++)
#pragma unroll
        for (int j = 0; j < 12; j++) acc[i][j] = 0.f;

    for (int dk = 0; dk < HID; dk += 32) {
        for (int t = tid; t < TQ * 32; t += 256) {
            int r = t >> 5, c = t & 31;
            QS[r * 33 + c] = qwB[(size_t)(q0 + r) * HID + dk + c];
        }
        for (int t = tid; t < TK * 32; t += 256) {
            int r = t >> 5, c = t & 31;
            int j = k0 + r;
            KS[r * 33 + c] = (j >= 0 && j < SEQ) ? reB[(size_t)j * HID + dk + c] : 0.f;
        }
        __syncthreads();

#pragma unroll 8
        for (int kk = 0; kk < 32; kk++) {
            float qv[4], kv[12];
#pragma unroll
            for (int i = 0; i < 4; i++)  qv[i] = QS[(4 * tr + i) * 33 + kk];
#pragma unroll
            for (int j = 0; j < 12; j++) kv[j] = KS[(12 * tc + j) * 33 + kk];
#pragma unroll
            for (int i = 0; i < 4; i++)
#pragma unroll
                for (int j = 0; j < 12; j++) acc[i][j] += qv[i] * kv[j];
        }
        __syncthreads();
    }

#pragma unroll
    for (int i = 0; i < 4; i++)
#pragma unroll
        for (int j = 0; j < 12; j++)
            S[(4 * tr + i) * SW + 12 * tc + j] = acc[i][j];
    __syncthreads();

    {
        const int row  = tid >> 2;
        const int quad = tid & 3;
        const int cbeg = quad * 48;
        const int i_gl = q0 + row;

        float mx = -3.4e38f;
#pragma unroll 8
        for (int c = cbeg; c < cbeg + 48; c++) {
            int j = k0 + c;
            int d = i_gl - j;
            bool valid = (j >= 0) && (j < SEQ) && (d <= WSIZE) && (d >= -WSIZE);
            float v = valid ? S[row * SW + c] : NEG_INF;
            S[row * SW + c] = v;
            mx = fmaxf(mx, v);
        }
        mx = fmaxf(mx, __shfl_xor_sync(0xffffffffu, mx, 1));
        mx = fmaxf(mx, __shfl_xor_sync(0xffffffffu, mx, 2));

        float sum = 0.f;
#pragma unroll 8
        for (int c = cbeg; c < cbeg + 48; c++) {
            float e = __expf(S[row * SW + c] - mx);
            S[row * SW + c] = e;
            sum += e;
        }
        sum += __shfl_xor_sync(0xffffffffu, sum, 1);
        sum += __shfl_xor_sync(0xffffffffu, sum, 2);
        float inv = 1.f / sum;
#pragma unroll 8
        for (int c = cbeg; c < cbeg + 48; c++)
            S[row * SW + c] *= inv;
    }
    __syncthreads();

    {
        const int rg = tid >> 3;
        const int cg = tid & 7;

        for (int d0 = 0; d0 < HID; d0 += 64) {
            for (int t = tid; t < TK * 64; t += 256) {
                int r = t >> 6, c = t & 63;
                int j = k0 + r;
                R[t] = (j >= 0 && j < SEQ) ? reB[(size_t)j * HID + d0 + c] : 0.f;
            }
            __syncthreads();

            float o0[8], o1[8];
#pragma unroll
            for (int u = 0; u < 8; u++) { o0[u] = 0.f; o1[u] = 0.f; }

#pragma unroll 4
            for (int k = 0; k < TK; k++) {
                float p0 = S[(2 * rg)     * SW + k];
                float p1 = S[(2 * rg + 1) * SW + k];
#pragma unroll
                for (int u = 0; u < 8; u++) {
                    float rv = R[k * 64 + 8 * cg + u];
                    o0[u] += p0 * rv;
                    o1[u] += p1 * rv;
                }
            }

            const int i0 = q0 + 2 * rg;
            const int c0 = d0 + 8 * cg;
#pragma unroll
            for (int u = 0; u < 8; u++) {
                oB[(size_t)i0 * HID + c0 + u] =
                    reB[(size_t)i0 * HID + c0 + u] + fmaxf(o0[u], 0.f);
                oB[(size_t)(i0 + 1) * HID + c0 + u] =
                    reB[(size_t)(i0 + 1) * HID + c0 + u] + fmaxf(o1[u], 0.f);
            }
            __syncthreads();
        }
    }
}

// ---------------------------------------------------------------------------
// Launch
// ---------------------------------------------------------------------------
extern "C" void kernel_launch(void* const* d_in, const int* in_sizes, int n_in,
                              void* d_out, int out_size)
{
    const float* repr = (const float*)d_in[0];   // [8, 2048, 1024]
    const float* W    = (const float*)d_in[1];   // [1024, 1024]
    float* out        = (float*)d_out;

    float* qw; __nv_bfloat16 *ah, *al, *bh, *bl;
    cudaGetSymbolAddress((void**)&qw, g_qw);
    cudaGetSymbolAddress((void**)&ah, g_ah);
    cudaGetSymbolAddress((void**)&al, g_al);
    cudaGetSymbolAddress((void**)&bh, g_bh);
    cudaGetSymbolAddress((void**)&bl, g_bl);

    // 1) bf16 splits
    split_repr_kernel<<<(BATCH * SEQ * HID) / (256 * 4), 256>>>(repr, ah, al);
    wsplit_kernel<<<(HID * HID) / 256, 256>>>(W, bh, bl);

    // 2) HMMA split-bf16 GEMM: qw = repr @ W
    {
        const int dyn = 2 * GS_SZ;   // 81920
        cudaFuncSetAttribute(gemm_hmma_kernel,
                             cudaFuncAttributeMaxDynamicSharedMemorySize, dyn);
        dim3 grid(HID / GBN, (BATCH * SEQ) / GBM);   // (8, 128)
        gemm_hmma_kernel<<<grid, 256, dyn>>>(ah, al, bh, bl, qw);
    }

    // 3) fused banded attention
    {
        const int smem_bytes = (TQ * SW + TK * 64) * (int)sizeof(float);
        cudaFuncSetAttribute(attn_kernel,
                             cudaFuncAttributeMaxDynamicSharedMemorySize, smem_bytes);
        dim3 grid(SEQ / TQ, BATCH);
        attn_kernel<<<grid, 256, smem_bytes>>>(qw, repr, out);
    }
}